// round 4
// baseline (speedup 1.0000x reference)
#include <cuda_runtime.h>
#include <cuda_fp16.h>
#include <cstdint>
#include <math.h>

#define Bb 2
#define Ss 2048
#define Dd 1024
#define NH 16
#define NKV 4
#define HD 64
#define MM (Bb*Ss)

// ---------------- scratch (__device__ globals) ------------------------------
__device__ __align__(16) __half g_xh [MM * Dd];
__device__ __align__(16) __half g_wh [1536 * Dd];
__device__ __align__(16) __half g_woh[Dd * 1024];
__device__ __align__(16) float  g_qkv[MM * 1536];
__device__ __align__(16) __half g_qh [Bb*NH *Ss*HD];
__device__ __align__(16) __half g_kh [Bb*NKV*Ss*HD];
__device__ __align__(16) __half g_vh [Bb*NKV*Ss*HD];
__device__ __align__(16) __half g_oh [MM * NH*HD];

// ---------------- warp-MMA helpers ------------------------------------------
__device__ __forceinline__ uint32_t smem_u32(const void* p) {
    uint32_t a;
    asm("{ .reg .u64 t; cvta.to.shared.u64 t, %1; cvt.u32.u64 %0, t; }" : "=r"(a) : "l"(p));
    return a;
}
__device__ __forceinline__ void mma16816(float* c, const uint32_t* a, uint32_t b0, uint32_t b1) {
    asm volatile("mma.sync.aligned.m16n8k16.row.col.f32.f16.f16.f32 "
                 "{%0,%1,%2,%3}, {%4,%5,%6,%7}, {%8,%9}, {%0,%1,%2,%3};"
                 : "+f"(c[0]), "+f"(c[1]), "+f"(c[2]), "+f"(c[3])
                 : "r"(a[0]), "r"(a[1]), "r"(a[2]), "r"(a[3]), "r"(b0), "r"(b1));
}
__device__ __forceinline__ void mma16816h(uint32_t* c, const uint32_t* a, uint32_t b0, uint32_t b1) {
    asm volatile("mma.sync.aligned.m16n8k16.row.col.f16.f16.f16.f16 "
                 "{%0,%1}, {%2,%3,%4,%5}, {%6,%7}, {%0,%1};"
                 : "+r"(c[0]), "+r"(c[1])
                 : "r"(a[0]), "r"(a[1]), "r"(a[2]), "r"(a[3]), "r"(b0), "r"(b1));
}
__device__ __forceinline__ void ldsm_x4(uint32_t* r, uint32_t a) {
    asm volatile("ldmatrix.sync.aligned.m8n8.x4.shared.b16 {%0,%1,%2,%3}, [%4];"
                 : "=r"(r[0]), "=r"(r[1]), "=r"(r[2]), "=r"(r[3]) : "r"(a));
}
__device__ __forceinline__ void ldsm_x4t(uint32_t* r, uint32_t a) {
    asm volatile("ldmatrix.sync.aligned.m8n8.x4.trans.shared.b16 {%0,%1,%2,%3}, [%4];"
                 : "=r"(r[0]), "=r"(r[1]), "=r"(r[2]), "=r"(r[3]) : "r"(a));
}
__device__ __forceinline__ uint32_t packh2(float x, float y) {
    __half2 h = __floats2half2_rn(x, y);
    return *reinterpret_cast<uint32_t*>(&h);
}

// ---------------- fused fp32->fp16 conversions (one launch) -----------------
__global__ void convall(const float* __restrict__ x,  const float* __restrict__ wq,
                        const float* __restrict__ wk, const float* __restrict__ wv,
                        const float* __restrict__ wo) {
    int i = blockIdx.x * blockDim.x + threadIdx.x;
    const float4* s; __half2* d;
    if      (i < 1048576) {                      s = (const float4*)x  + i; d = (__half2*)g_xh            + 2 * i; }
    else if (i < 1310720) { int t = i - 1048576; s = (const float4*)wq + t; d = (__half2*)g_wh            + 2 * t; }
    else if (i < 1376256) { int t = i - 1310720; s = (const float4*)wk + t; d = (__half2*)(g_wh + 1048576) + 2 * t; }
    else if (i < 1441792) { int t = i - 1376256; s = (const float4*)wv + t; d = (__half2*)(g_wh + 1310720) + 2 * t; }
    else if (i < 1703936) { int t = i - 1441792; s = (const float4*)wo + t; d = (__half2*)g_woh           + 2 * t; }
    else return;
    float4 v = *s;
    d[0] = __floats2half2_rn(v.x, v.y);
    d[1] = __floats2half2_rn(v.z, v.w);
}

// ---------------- HMMA GEMM: C[M,N] = A[M,K]*B[N,K]^T ----------------------
#define AST 40
__global__ __launch_bounds__(256) void gemm_f16(const __half* __restrict__ A,
                                                const __half* __restrict__ B,
                                                float* __restrict__ C,
                                                int N, int K) {
    __shared__ __align__(16) __half As[2][128 * AST];
    __shared__ __align__(16) __half Bs[2][128 * AST];
    const int tid = threadIdx.x, lane = tid & 31, wid = tid >> 5;
    const int wm = wid & 1, wn = wid >> 1;
    const int m0 = blockIdx.y * 128, n0 = blockIdx.x * 128;
    const int gid = lane >> 2, tig = lane & 3;

    float acc[4][4][4];
#pragma unroll
    for (int mi = 0; mi < 4; mi++)
#pragma unroll
        for (int ni = 0; ni < 4; ni++)
#pragma unroll
            for (int j = 0; j < 4; j++) acc[mi][ni][j] = 0.f;

    const int r0c = tid >> 2, c0c = tid & 3;
    const int r1c = (tid + 256) >> 2, c1c = (tid + 256) & 3;

    const int NKt = K >> 5;
    *(uint4*)&As[0][r0c * AST + c0c * 8] = *(const uint4*)(A + (size_t)(m0 + r0c) * K + c0c * 8);
    *(uint4*)&As[0][r1c * AST + c1c * 8] = *(const uint4*)(A + (size_t)(m0 + r1c) * K + c1c * 8);
    *(uint4*)&Bs[0][r0c * AST + c0c * 8] = *(const uint4*)(B + (size_t)(n0 + r0c) * K + c0c * 8);
    *(uint4*)&Bs[0][r1c * AST + c1c * 8] = *(const uint4*)(B + (size_t)(n0 + r1c) * K + c1c * 8);
    __syncthreads();

    const uint32_t asb0 = smem_u32(As), bsb0 = smem_u32(Bs);
    for (int kt = 0; kt < NKt; kt++) {
        const int buf = kt & 1;
        uint4 pa0, pa1, pb0, pb1;
        if (kt + 1 < NKt) {
            const int k0 = (kt + 1) << 5;
            pa0 = *(const uint4*)(A + (size_t)(m0 + r0c) * K + k0 + c0c * 8);
            pa1 = *(const uint4*)(A + (size_t)(m0 + r1c) * K + k0 + c1c * 8);
            pb0 = *(const uint4*)(B + (size_t)(n0 + r0c) * K + k0 + c0c * 8);
            pb1 = *(const uint4*)(B + (size_t)(n0 + r1c) * K + k0 + c1c * 8);
        }
        const uint32_t asb = asb0 + buf * (128 * AST * 2);
        const uint32_t bsb = bsb0 + buf * (128 * AST * 2);
#pragma unroll
        for (int ks = 0; ks < 2; ks++) {
            uint32_t af[4][4];
#pragma unroll
            for (int mi = 0; mi < 4; mi++)
                ldsm_x4(af[mi], asb + (((wm * 64 + mi * 16 + (lane & 15)) * AST
                                        + ks * 16 + (lane >> 4) * 8) << 1));
            uint32_t bfr[2][4];
#pragma unroll
            for (int ni2 = 0; ni2 < 2; ni2++)
                ldsm_x4(bfr[ni2], bsb + (((wn * 32 + ni2 * 16 + (lane & 15)) * AST
                                          + ks * 16 + (lane >> 4) * 8) << 1));
#pragma unroll
            for (int ni = 0; ni < 4; ni++) {
                const uint32_t b0 = bfr[ni >> 1][ni & 1], b1 = bfr[ni >> 1][(ni & 1) + 2];
#pragma unroll
                for (int mi = 0; mi < 4; mi++) mma16816(acc[mi][ni], af[mi], b0, b1);
            }
        }
        if (kt + 1 < NKt) {
            const int nb = buf ^ 1;
            *(uint4*)&As[nb][r0c * AST + c0c * 8] = pa0;
            *(uint4*)&As[nb][r1c * AST + c1c * 8] = pa1;
            *(uint4*)&Bs[nb][r0c * AST + c0c * 8] = pb0;
            *(uint4*)&Bs[nb][r1c * AST + c1c * 8] = pb1;
        }
        __syncthreads();
    }

#pragma unroll
    for (int mi = 0; mi < 4; mi++)
#pragma unroll
        for (int ni = 0; ni < 4; ni++) {
            const int row = m0 + wm * 64 + mi * 16 + gid;
            const int col = n0 + wn * 32 + ni * 8 + tig * 2;
            *(float2*)&C[(size_t)row * N + col]       = make_float2(acc[mi][ni][0], acc[mi][ni][1]);
            *(float2*)&C[(size_t)(row + 8) * N + col] = make_float2(acc[mi][ni][2], acc[mi][ni][3]);
        }
}

// ---------------- fused RoPE + V layout (one launch) -------------------------
__global__ void prep(const float* __restrict__ qkv) {
    int idx = blockIdx.x * blockDim.x + threadIdx.x;
    if (idx < MM * NH * 32) {
        int j = idx & 31, hh = (idx >> 5) & 15, row = idx >> 9;
        int s = row & (Ss - 1), b = row >> 11;
        float ang = (float)s * expf(-(float)j * (9.210340371976184f / 32.f));
        float sn, cs; sincosf(ang, &sn, &cs);
        const float* p = qkv + (size_t)row * 1536 + hh * 64;
        float x1 = p[j], x2 = p[j + 32];
        __half* o = g_qh + ((size_t)(b * NH + hh) * Ss + s) * HD;
        o[j]      = __float2half((x1 * cs - x2 * sn) * 0.125f);
        o[j + 32] = __float2half((x2 * cs + x1 * sn) * 0.125f);
    } else if (idx < MM * NH * 32 + MM * NKV * 32) {
        int t = idx - MM * NH * 32;
        int j = t & 31, hh = (t >> 5) & 3, row = t >> 7;
        int s = row & (Ss - 1), b = row >> 11;
        float ang = (float)s * expf(-(float)j * (9.210340371976184f / 32.f));
        float sn, cs; sincosf(ang, &sn, &cs);
        const float* p = qkv + (size_t)row * 1536 + 1024 + hh * 64;
        float x1 = p[j], x2 = p[j + 32];
        __half* o = g_kh + ((size_t)(b * NKV + hh) * Ss + s) * HD;
        o[j]      = __float2half(x1 * cs - x2 * sn);
        o[j + 32] = __float2half(x2 * cs + x1 * sn);
    } else if (idx < MM * NH * 32 + MM * NKV * 32 + MM * NKV * 16) {
        int t = idx - (MM * NH * 32 + MM * NKV * 32);
        int d4 = t & 15, hh = (t >> 4) & 3, row = t >> 6;
        int s = row & (Ss - 1), b = row >> 11;
        float4 v = *(const float4*)(qkv + (size_t)row * 1536 + 1280 + hh * 64 + d4 * 4);
        __half2* o = (__half2*)(g_vh + ((size_t)(b * NKV + hh) * Ss + s) * HD + d4 * 4);
        o[0] = __floats2half2_rn(v.x, v.y);
        o[1] = __floats2half2_rn(v.z, v.w);
    }
}

// ---------------- flash attention (HMMA, Q-tile 128, 8 warps) ----------------
#define FST 72
__global__ __launch_bounds__(256) void flash_f16() {
    __shared__ __align__(16) __half Qs[128 * FST];
    __shared__ __align__(16) __half Ks[64 * FST];
    __shared__ __align__(16) __half Vs[64 * FST];
    const int tid = threadIdx.x, lane = tid & 31, w = tid >> 5;
    const int qt = (gridDim.x - 1) - blockIdx.x;     // heavy blocks first
    const int h = blockIdx.y, b = blockIdx.z;
    const int qm0 = qt * 128, kvh = h >> 2, qw0 = w * 16;
    const int gid = lane >> 2, tig = lane & 3;

    const __half* qb = g_qh + ((size_t)(b * NH + h) * Ss + qm0) * HD;
#pragma unroll
    for (int i = 0; i < 4; i++) {
        int u = tid + i * 256, r = u >> 3, c = u & 7;
        *(uint4*)&Qs[r * FST + c * 8] = *(const uint4*)(qb + (size_t)r * HD + c * 8);
    }
    __syncthreads();

    const uint32_t qsb = smem_u32(Qs), ksb = smem_u32(Ks), vsb = smem_u32(Vs);
    uint32_t aQ[4][4];
#pragma unroll
    for (int ks = 0; ks < 4; ks++)
        ldsm_x4(aQ[ks], qsb + (((qw0 + (lane & 15)) * FST + ks * 16 + (lane >> 4) * 8) << 1));

    const __half* kb = g_kh + (size_t)(b * NKV + kvh) * Ss * HD;
    const __half* vb = g_vh + (size_t)(b * NKV + kvh) * Ss * HD;

    float oacc[8][4];
#pragma unroll
    for (int ni = 0; ni < 8; ni++)
#pragma unroll
        for (int j = 0; j < 4; j++) oacc[ni][j] = 0.f;
    float m0_ = -1e30f, m1_ = -1e30f, l0_ = 0.f, l1_ = 0.f;
    const int row0 = qm0 + qw0 + gid, row1 = row0 + 8;

    const int ntiles = 2 * qt + 2;
    for (int t = 0; t < ntiles; t++) {
        const int n0 = t * 64;
#pragma unroll
        for (int i = 0; i < 4; i++) {
            int u = tid + i * 256, r = u >> 3, c = u & 7;
            if (i < 2) *(uint4*)&Ks[r * FST + c * 8] = *(const uint4*)(kb + (size_t)(n0 + r) * HD + c * 8);
            else       *(uint4*)&Vs[(r - 64) * FST + c * 8] = *(const uint4*)(vb + (size_t)(n0 + r - 64) * HD + c * 8);
        }
        __syncthreads();

        // S = Q K^T in fp16 accumulation
        uint32_t sh[8][2];
#pragma unroll
        for (int ni = 0; ni < 8; ni++) { sh[ni][0] = 0u; sh[ni][1] = 0u; }
#pragma unroll
        for (int ks = 0; ks < 4; ks++)
#pragma unroll
            for (int ni2 = 0; ni2 < 4; ni2++) {
                uint32_t kr[4];
                ldsm_x4(kr, ksb + (((ni2 * 16 + (lane & 15)) * FST + ks * 16 + (lane >> 4) * 8) << 1));
                mma16816h(sh[ni2 * 2],     aQ[ks], kr[0], kr[2]);
                mma16816h(sh[ni2 * 2 + 1], aQ[ks], kr[1], kr[3]);
            }

        float sacc[8][4];
#pragma unroll
        for (int ni = 0; ni < 8; ni++) {
            float2 lo = __half22float2(*reinterpret_cast<__half2*>(&sh[ni][0]));
            float2 hi = __half22float2(*reinterpret_cast<__half2*>(&sh[ni][1]));
            sacc[ni][0] = lo.x; sacc[ni][1] = lo.y; sacc[ni][2] = hi.x; sacc[ni][3] = hi.y;
        }
        if (n0 + 63 > row0) {
#pragma unroll
            for (int ni = 0; ni < 8; ni++) {
                const int col = n0 + ni * 8 + tig * 2;
                if (col     > row0) sacc[ni][0] = -1e30f;
                if (col + 1 > row0) sacc[ni][1] = -1e30f;
                if (col     > row1) sacc[ni][2] = -1e30f;
                if (col + 1 > row1) sacc[ni][3] = -1e30f;
            }
        }

        float mx0 = -1e30f, mx1 = -1e30f;
#pragma unroll
        for (int ni = 0; ni < 8; ni++) {
            mx0 = fmaxf(mx0, fmaxf(sacc[ni][0], sacc[ni][1]));
            mx1 = fmaxf(mx1, fmaxf(sacc[ni][2], sacc[ni][3]));
        }
        mx0 = fmaxf(mx0, __shfl_xor_sync(0xffffffffu, mx0, 1));
        mx0 = fmaxf(mx0, __shfl_xor_sync(0xffffffffu, mx0, 2));
        mx1 = fmaxf(mx1, __shfl_xor_sync(0xffffffffu, mx1, 1));
        mx1 = fmaxf(mx1, __shfl_xor_sync(0xffffffffu, mx1, 2));
        const float mn0 = fmaxf(m0_, mx0), mn1 = fmaxf(m1_, mx1);
        const float al0 = __expf(m0_ - mn0), al1 = __expf(m1_ - mn1);
        float s0 = 0.f, s1 = 0.f;
#pragma unroll
        for (int ni = 0; ni < 8; ni++) {
            sacc[ni][0] = __expf(sacc[ni][0] - mn0);
            sacc[ni][1] = __expf(sacc[ni][1] - mn0);
            sacc[ni][2] = __expf(sacc[ni][2] - mn1);
            sacc[ni][3] = __expf(sacc[ni][3] - mn1);
            s0 += sacc[ni][0] + sacc[ni][1];
            s1 += sacc[ni][2] + sacc[ni][3];
        }
        s0 += __shfl_xor_sync(0xffffffffu, s0, 1);
        s0 += __shfl_xor_sync(0xffffffffu, s0, 2);
        s1 += __shfl_xor_sync(0xffffffffu, s1, 1);
        s1 += __shfl_xor_sync(0xffffffffu, s1, 2);
        l0_ = l0_ * al0 + s0; l1_ = l1_ * al1 + s1;
        m0_ = mn0; m1_ = mn1;

        uint32_t aP[4][4];
#pragma unroll
        for (int ks = 0; ks < 4; ks++) {
            aP[ks][0] = packh2(sacc[2 * ks][0],     sacc[2 * ks][1]);
            aP[ks][1] = packh2(sacc[2 * ks][2],     sacc[2 * ks][3]);
            aP[ks][2] = packh2(sacc[2 * ks + 1][0], sacc[2 * ks + 1][1]);
            aP[ks][3] = packh2(sacc[2 * ks + 1][2], sacc[2 * ks + 1][3]);
        }
#pragma unroll
        for (int ni = 0; ni < 8; ni++) {
            oacc[ni][0] *= al0; oacc[ni][1] *= al0;
            oacc[ni][2] *= al1; oacc[ni][3] *= al1;
        }
#pragma unroll
        for (int ks = 0; ks < 4; ks++)
#pragma unroll
            for (int ni2 = 0; ni2 < 4; ni2++) {
                uint32_t vr[4];
                ldsm_x4t(vr, vsb + (((ks * 16 + ((lane >> 3) & 1) * 8 + (lane & 7)) * FST
                                     + ni2 * 16 + (lane >> 4) * 8) << 1));
                mma16816(oacc[ni2 * 2],     aP[ks], vr[0], vr[1]);
                mma16816(oacc[ni2 * 2 + 1], aP[ks], vr[2], vr[3]);
            }
        __syncthreads();
    }

    const float inv0 = 1.f / l0_, inv1 = 1.f / l1_;
    __half* ob = g_oh + (size_t)(b * Ss + qm0 + qw0) * (NH * HD) + h * HD;
#pragma unroll
    for (int ni = 0; ni < 8; ni++) {
        const int col = ni * 8 + tig * 2;
        __half2 o0 = __floats2half2_rn(oacc[ni][0] * inv0, oacc[ni][1] * inv0);
        __half2 o1 = __floats2half2_rn(oacc[ni][2] * inv1, oacc[ni][3] * inv1);
        *(__half2*)&ob[(size_t)gid * (NH * HD) + col]       = o0;
        *(__half2*)&ob[(size_t)(gid + 8) * (NH * HD) + col] = o1;
    }
}

// ---------------------------------------------------------------------------
extern "C" void kernel_launch(void* const* d_in, const int* in_sizes, int n_in,
                              void* d_out, int out_size) {
    const float* x  = (const float*)d_in[0];
    const float* Wq = (const float*)d_in[1];
    const float* Wk = (const float*)d_in[2];
    const float* Wv = (const float*)d_in[3];
    const float* Wo = (const float*)d_in[4];
    float* out = (float*)d_out;

    __half *xh, *wh, *woh, *oh;
    float* qkv;
    cudaGetSymbolAddress((void**)&xh,  g_xh);
    cudaGetSymbolAddress((void**)&wh,  g_wh);
    cudaGetSymbolAddress((void**)&woh, g_woh);
    cudaGetSymbolAddress((void**)&qkv, g_qkv);
    cudaGetSymbolAddress((void**)&oh,  g_oh);

    convall<<<(1703936 + 255) / 256, 256>>>(x, Wq, Wk, Wv, Wo);
    gemm_f16<<<dim3(12, 32), 256>>>(xh, wh, qkv, 1536, 1024);
    prep<<<(MM * NH * 32 + MM * NKV * 32 + MM * NKV * 16 + 255) / 256, 256>>>(qkv);
    flash_f16<<<dim3(16, NH, Bb), 256>>>();
    gemm_f16<<<dim3(8, 32), 256>>>(oh, woh, out, 1024, 1024);
}

// round 5
// speedup vs baseline: 1.0606x; 1.0606x over previous
#include <cuda_runtime.h>
#include <cuda_fp16.h>
#include <cstdint>
#include <math.h>

#define Bb 2
#define Ss 2048
#define Dd 1024
#define NH 16
#define NKV 4
#define HD 64
#define MM (Bb*Ss)

// ---------------- scratch (__device__ globals) ------------------------------
__device__ __align__(16) __half g_xh [MM * Dd];
__device__ __align__(16) __half g_wh [1536 * Dd];
__device__ __align__(16) __half g_woh[Dd * 1024];
__device__ __align__(16) float  g_qkv[MM * 1536];
__device__ __align__(16) __half g_qh [Bb*NH *Ss*HD];
__device__ __align__(16) __half g_kh [Bb*NKV*Ss*HD];
__device__ __align__(16) __half g_vh [Bb*NKV*Ss*HD];
__device__ __align__(16) __half g_oh [MM * NH*HD];

// ---------------- warp-MMA helpers ------------------------------------------
__device__ __forceinline__ uint32_t smem_u32(const void* p) {
    uint32_t a;
    asm("{ .reg .u64 t; cvta.to.shared.u64 t, %1; cvt.u32.u64 %0, t; }" : "=r"(a) : "l"(p));
    return a;
}
__device__ __forceinline__ void mma16816(float* c, const uint32_t* a, uint32_t b0, uint32_t b1) {
    asm volatile("mma.sync.aligned.m16n8k16.row.col.f32.f16.f16.f32 "
                 "{%0,%1,%2,%3}, {%4,%5,%6,%7}, {%8,%9}, {%0,%1,%2,%3};"
                 : "+f"(c[0]), "+f"(c[1]), "+f"(c[2]), "+f"(c[3])
                 : "r"(a[0]), "r"(a[1]), "r"(a[2]), "r"(a[3]), "r"(b0), "r"(b1));
}
__device__ __forceinline__ void mma16816h(uint32_t* c, const uint32_t* a, uint32_t b0, uint32_t b1) {
    asm volatile("mma.sync.aligned.m16n8k16.row.col.f16.f16.f16.f16 "
                 "{%0,%1}, {%2,%3,%4,%5}, {%6,%7}, {%0,%1};"
                 : "+r"(c[0]), "+r"(c[1])
                 : "r"(a[0]), "r"(a[1]), "r"(a[2]), "r"(a[3]), "r"(b0), "r"(b1));
}
__device__ __forceinline__ void ldsm_x4(uint32_t* r, uint32_t a) {
    asm volatile("ldmatrix.sync.aligned.m8n8.x4.shared.b16 {%0,%1,%2,%3}, [%4];"
                 : "=r"(r[0]), "=r"(r[1]), "=r"(r[2]), "=r"(r[3]) : "r"(a));
}
__device__ __forceinline__ void ldsm_x4t(uint32_t* r, uint32_t a) {
    asm volatile("ldmatrix.sync.aligned.m8n8.x4.trans.shared.b16 {%0,%1,%2,%3}, [%4];"
                 : "=r"(r[0]), "=r"(r[1]), "=r"(r[2]), "=r"(r[3]) : "r"(a));
}
__device__ __forceinline__ uint32_t packh2(float x, float y) {
    __half2 h = __floats2half2_rn(x, y);
    return *reinterpret_cast<uint32_t*>(&h);
}
__device__ __forceinline__ void cp16(uint32_t dst, const void* src) {
    asm volatile("cp.async.cg.shared.global [%0], [%1], 16;" :: "r"(dst), "l"(src));
}

// ---------------- fused fp32->fp16 conversions (one launch) -----------------
__global__ void convall(const float* __restrict__ x,  const float* __restrict__ wq,
                        const float* __restrict__ wk, const float* __restrict__ wv,
                        const float* __restrict__ wo) {
    int i = blockIdx.x * blockDim.x + threadIdx.x;
    const float4* s; __half2* d;
    if      (i < 1048576) {                      s = (const float4*)x  + i; d = (__half2*)g_xh            + 2 * i; }
    else if (i < 1310720) { int t = i - 1048576; s = (const float4*)wq + t; d = (__half2*)g_wh            + 2 * t; }
    else if (i < 1376256) { int t = i - 1310720; s = (const float4*)wk + t; d = (__half2*)(g_wh + 1048576) + 2 * t; }
    else if (i < 1441792) { int t = i - 1376256; s = (const float4*)wv + t; d = (__half2*)(g_wh + 1310720) + 2 * t; }
    else if (i < 1703936) { int t = i - 1441792; s = (const float4*)wo + t; d = (__half2*)g_woh           + 2 * t; }
    else return;
    float4 v = *s;
    d[0] = __floats2half2_rn(v.x, v.y);
    d[1] = __floats2half2_rn(v.z, v.w);
}

// ---------------- HMMA GEMM: C[M,N] = A[M,K]*B[N,K]^T ----------------------
#define AST 40
__global__ __launch_bounds__(256) void gemm_f16(const __half* __restrict__ A,
                                                const __half* __restrict__ B,
                                                float* __restrict__ C,
                                                int N, int K) {
    __shared__ __align__(16) __half As[2][128 * AST];
    __shared__ __align__(16) __half Bs[2][128 * AST];
    const int tid = threadIdx.x, lane = tid & 31, wid = tid >> 5;
    const int wm = wid & 1, wn = wid >> 1;
    const int m0 = blockIdx.y * 128, n0 = blockIdx.x * 128;
    const int gid = lane >> 2, tig = lane & 3;

    float acc[4][4][4];
#pragma unroll
    for (int mi = 0; mi < 4; mi++)
#pragma unroll
        for (int ni = 0; ni < 4; ni++)
#pragma unroll
            for (int j = 0; j < 4; j++) acc[mi][ni][j] = 0.f;

    const int r0c = tid >> 2, c0c = tid & 3;
    const int r1c = (tid + 256) >> 2, c1c = (tid + 256) & 3;

    const int NKt = K >> 5;
    *(uint4*)&As[0][r0c * AST + c0c * 8] = *(const uint4*)(A + (size_t)(m0 + r0c) * K + c0c * 8);
    *(uint4*)&As[0][r1c * AST + c1c * 8] = *(const uint4*)(A + (size_t)(m0 + r1c) * K + c1c * 8);
    *(uint4*)&Bs[0][r0c * AST + c0c * 8] = *(const uint4*)(B + (size_t)(n0 + r0c) * K + c0c * 8);
    *(uint4*)&Bs[0][r1c * AST + c1c * 8] = *(const uint4*)(B + (size_t)(n0 + r1c) * K + c1c * 8);
    __syncthreads();

    const uint32_t asb0 = smem_u32(As), bsb0 = smem_u32(Bs);
    for (int kt = 0; kt < NKt; kt++) {
        const int buf = kt & 1;
        uint4 pa0, pa1, pb0, pb1;
        if (kt + 1 < NKt) {
            const int k0 = (kt + 1) << 5;
            pa0 = *(const uint4*)(A + (size_t)(m0 + r0c) * K + k0 + c0c * 8);
            pa1 = *(const uint4*)(A + (size_t)(m0 + r1c) * K + k0 + c1c * 8);
            pb0 = *(const uint4*)(B + (size_t)(n0 + r0c) * K + k0 + c0c * 8);
            pb1 = *(const uint4*)(B + (size_t)(n0 + r1c) * K + k0 + c1c * 8);
        }
        const uint32_t asb = asb0 + buf * (128 * AST * 2);
        const uint32_t bsb = bsb0 + buf * (128 * AST * 2);
#pragma unroll
        for (int ks = 0; ks < 2; ks++) {
            uint32_t af[4][4];
#pragma unroll
            for (int mi = 0; mi < 4; mi++)
                ldsm_x4(af[mi], asb + (((wm * 64 + mi * 16 + (lane & 15)) * AST
                                        + ks * 16 + (lane >> 4) * 8) << 1));
            uint32_t bfr[2][4];
#pragma unroll
            for (int ni2 = 0; ni2 < 2; ni2++)
                ldsm_x4(bfr[ni2], bsb + (((wn * 32 + ni2 * 16 + (lane & 15)) * AST
                                          + ks * 16 + (lane >> 4) * 8) << 1));
#pragma unroll
            for (int ni = 0; ni < 4; ni++) {
                const uint32_t b0 = bfr[ni >> 1][ni & 1], b1 = bfr[ni >> 1][(ni & 1) + 2];
#pragma unroll
                for (int mi = 0; mi < 4; mi++) mma16816(acc[mi][ni], af[mi], b0, b1);
            }
        }
        if (kt + 1 < NKt) {
            const int nb = buf ^ 1;
            *(uint4*)&As[nb][r0c * AST + c0c * 8] = pa0;
            *(uint4*)&As[nb][r1c * AST + c1c * 8] = pa1;
            *(uint4*)&Bs[nb][r0c * AST + c0c * 8] = pb0;
            *(uint4*)&Bs[nb][r1c * AST + c1c * 8] = pb1;
        }
        __syncthreads();
    }

#pragma unroll
    for (int mi = 0; mi < 4; mi++)
#pragma unroll
        for (int ni = 0; ni < 4; ni++) {
            const int row = m0 + wm * 64 + mi * 16 + gid;
            const int col = n0 + wn * 32 + ni * 8 + tig * 2;
            *(float2*)&C[(size_t)row * N + col]       = make_float2(acc[mi][ni][0], acc[mi][ni][1]);
            *(float2*)&C[(size_t)(row + 8) * N + col] = make_float2(acc[mi][ni][2], acc[mi][ni][3]);
        }
}

// ---------------- fused RoPE + V layout (one launch) -------------------------
__global__ void prep(const float* __restrict__ qkv) {
    int idx = blockIdx.x * blockDim.x + threadIdx.x;
    if (idx < MM * NH * 32) {
        int j = idx & 31, hh = (idx >> 5) & 15, row = idx >> 9;
        int s = row & (Ss - 1), b = row >> 11;
        float ang = (float)s * expf(-(float)j * (9.210340371976184f / 32.f));
        float sn, cs; sincosf(ang, &sn, &cs);
        const float* p = qkv + (size_t)row * 1536 + hh * 64;
        float x1 = p[j], x2 = p[j + 32];
        __half* o = g_qh + ((size_t)(b * NH + hh) * Ss + s) * HD;
        o[j]      = __float2half((x1 * cs - x2 * sn) * 0.125f);
        o[j + 32] = __float2half((x2 * cs + x1 * sn) * 0.125f);
    } else if (idx < MM * NH * 32 + MM * NKV * 32) {
        int t = idx - MM * NH * 32;
        int j = t & 31, hh = (t >> 5) & 3, row = t >> 7;
        int s = row & (Ss - 1), b = row >> 11;
        float ang = (float)s * expf(-(float)j * (9.210340371976184f / 32.f));
        float sn, cs; sincosf(ang, &sn, &cs);
        const float* p = qkv + (size_t)row * 1536 + 1024 + hh * 64;
        float x1 = p[j], x2 = p[j + 32];
        __half* o = g_kh + ((size_t)(b * NKV + hh) * Ss + s) * HD;
        o[j]      = __float2half(x1 * cs - x2 * sn);
        o[j + 32] = __float2half(x2 * cs + x1 * sn);
    } else if (idx < MM * NH * 32 + MM * NKV * 32 + MM * NKV * 16) {
        int t = idx - (MM * NH * 32 + MM * NKV * 32);
        int d4 = t & 15, hh = (t >> 4) & 3, row = t >> 6;
        int s = row & (Ss - 1), b = row >> 11;
        float4 v = *(const float4*)(qkv + (size_t)row * 1536 + 1280 + hh * 64 + d4 * 4);
        __half2* o = (__half2*)(g_vh + ((size_t)(b * NKV + hh) * Ss + s) * HD + d4 * 4);
        o[0] = __floats2half2_rn(v.x, v.y);
        o[1] = __floats2half2_rn(v.z, v.w);
    }
}

// ---------------- flash attention (HMMA + cp.async pipeline) -----------------
// grid(16, NH, Bb), 256 threads (8 warps x 16 q-rows), KV tile 64, 2-stage.
// dyn smem: Q 18432 | K[2] 2*9216 | V[2] 2*9216 = 55296 B
#define FST 72
#define FLASH_SMEM 55296
__global__ __launch_bounds__(256) void flash_f16() {
    extern __shared__ __align__(16) char sm[];
    __half* Qs = (__half*)sm;
    const uint32_t qsb = smem_u32(sm);
    const uint32_t ksb0 = qsb + 18432, vsb0 = qsb + 36864;

    const int tid = threadIdx.x, lane = tid & 31, w = tid >> 5;
    const int qt = (gridDim.x - 1) - blockIdx.x;     // heavy blocks first
    const int h = blockIdx.y, b = blockIdx.z;
    const int qm0 = qt * 128, kvh = h >> 2, qw0 = w * 16;
    const int gid = lane >> 2, tig = lane & 3;

    const __half* kb = g_kh + (size_t)(b * NKV + kvh) * Ss * HD;
    const __half* vb = g_vh + (size_t)(b * NKV + kvh) * Ss * HD;
    const int cr = tid >> 3, cc = (tid & 7) * 8;     // cp.async row/col per thread

    // prologue: tile 0 -> buf 0 via cp.async, Q direct
    cp16(ksb0 + ((cr * FST + cc) << 1), kb + (size_t)cr * HD + cc);
    cp16(ksb0 + (((cr + 32) * FST + cc) << 1), kb + (size_t)(cr + 32) * HD + cc);
    cp16(vsb0 + ((cr * FST + cc) << 1), vb + (size_t)cr * HD + cc);
    cp16(vsb0 + (((cr + 32) * FST + cc) << 1), vb + (size_t)(cr + 32) * HD + cc);
    asm volatile("cp.async.commit_group;");

    const __half* qb = g_qh + ((size_t)(b * NH + h) * Ss + qm0) * HD;
#pragma unroll
    for (int i = 0; i < 4; i++) {
        int u = tid + i * 256, r = u >> 3, c = u & 7;
        *(uint4*)&Qs[r * FST + c * 8] = *(const uint4*)(qb + (size_t)r * HD + c * 8);
    }
    asm volatile("cp.async.wait_group 0;" ::: "memory");
    __syncthreads();

    uint32_t aQ[4][4];
#pragma unroll
    for (int ks = 0; ks < 4; ks++)
        ldsm_x4(aQ[ks], qsb + (((qw0 + (lane & 15)) * FST + ks * 16 + (lane >> 4) * 8) << 1));

    float oacc[8][4];
#pragma unroll
    for (int ni = 0; ni < 8; ni++)
#pragma unroll
        for (int j = 0; j < 4; j++) oacc[ni][j] = 0.f;
    float m0_ = -1e30f, m1_ = -1e30f, l0_ = 0.f, l1_ = 0.f;
    const int row0 = qm0 + qw0 + gid, row1 = row0 + 8;

    const int ntiles = 2 * qt + 2;
    for (int t = 0; t < ntiles; t++) {
        const int n0 = t * 64;
        const int buf = t & 1;
        if (t + 1 < ntiles) {
            const int nn = n0 + 64;
            const uint32_t kd = ksb0 + (buf ^ 1) * 9216, vd = vsb0 + (buf ^ 1) * 9216;
            cp16(kd + ((cr * FST + cc) << 1), kb + (size_t)(nn + cr) * HD + cc);
            cp16(kd + (((cr + 32) * FST + cc) << 1), kb + (size_t)(nn + cr + 32) * HD + cc);
            cp16(vd + ((cr * FST + cc) << 1), vb + (size_t)(nn + cr) * HD + cc);
            cp16(vd + (((cr + 32) * FST + cc) << 1), vb + (size_t)(nn + cr + 32) * HD + cc);
            asm volatile("cp.async.commit_group;");
        }

        if (qm0 + qw0 + 15 >= n0) {     // warp has at least one unmasked row
            const uint32_t ksb = ksb0 + buf * 9216, vsb = vsb0 + buf * 9216;

            // S = Q K^T in fp16 accumulation
            uint32_t sh[8][2];
#pragma unroll
            for (int ni = 0; ni < 8; ni++) { sh[ni][0] = 0u; sh[ni][1] = 0u; }
#pragma unroll
            for (int ks = 0; ks < 4; ks++)
#pragma unroll
                for (int ni2 = 0; ni2 < 4; ni2++) {
                    uint32_t kr[4];
                    ldsm_x4(kr, ksb + (((ni2 * 16 + (lane & 15)) * FST + ks * 16 + (lane >> 4) * 8) << 1));
                    mma16816h(sh[ni2 * 2],     aQ[ks], kr[0], kr[2]);
                    mma16816h(sh[ni2 * 2 + 1], aQ[ks], kr[1], kr[3]);
                }

            float sacc[8][4];
#pragma unroll
            for (int ni = 0; ni < 8; ni++) {
                float2 lo = __half22float2(*reinterpret_cast<__half2*>(&sh[ni][0]));
                float2 hi = __half22float2(*reinterpret_cast<__half2*>(&sh[ni][1]));
                sacc[ni][0] = lo.x; sacc[ni][1] = lo.y; sacc[ni][2] = hi.x; sacc[ni][3] = hi.y;
            }
            if (n0 + 63 > row0) {
#pragma unroll
                for (int ni = 0; ni < 8; ni++) {
                    const int col = n0 + ni * 8 + tig * 2;
                    if (col     > row0) sacc[ni][0] = -1e30f;
                    if (col + 1 > row0) sacc[ni][1] = -1e30f;
                    if (col     > row1) sacc[ni][2] = -1e30f;
                    if (col + 1 > row1) sacc[ni][3] = -1e30f;
                }
            }

            // packed-half2 max reduction (2 shfl instead of 4)
            float mx0 = -1e30f, mx1 = -1e30f;
#pragma unroll
            for (int ni = 0; ni < 8; ni++) {
                mx0 = fmaxf(mx0, fmaxf(sacc[ni][0], sacc[ni][1]));
                mx1 = fmaxf(mx1, fmaxf(sacc[ni][2], sacc[ni][3]));
            }
            __half2 mp = __floats2half2_rn(mx0, mx1);
            {
                uint32_t mu = *reinterpret_cast<uint32_t*>(&mp);
                uint32_t o1 = __shfl_xor_sync(0xffffffffu, mu, 1);
                mp = __hmax2(mp, *reinterpret_cast<__half2*>(&o1));
                mu = *reinterpret_cast<uint32_t*>(&mp);
                uint32_t o2 = __shfl_xor_sync(0xffffffffu, mu, 2);
                mp = __hmax2(mp, *reinterpret_cast<__half2*>(&o2));
            }
            float2 mf = __half22float2(mp);
            const float mn0 = fmaxf(m0_, mf.x), mn1 = fmaxf(m1_, mf.y);
            const float al0 = __expf(m0_ - mn0), al1 = __expf(m1_ - mn1);

            float s0 = 0.f, s1 = 0.f;
#pragma unroll
            for (int ni = 0; ni < 8; ni++) {
                sacc[ni][0] = __expf(sacc[ni][0] - mn0);
                sacc[ni][1] = __expf(sacc[ni][1] - mn0);
                sacc[ni][2] = __expf(sacc[ni][2] - mn1);
                sacc[ni][3] = __expf(sacc[ni][3] - mn1);
                s0 += sacc[ni][0] + sacc[ni][1];
                s1 += sacc[ni][2] + sacc[ni][3];
            }
            l0_ = l0_ * al0 + s0;          // per-lane partial; reduced in epilogue
            l1_ = l1_ * al1 + s1;
            m0_ = mn0; m1_ = mn1;

            uint32_t aP[4][4];
#pragma unroll
            for (int ks = 0; ks < 4; ks++) {
                aP[ks][0] = packh2(sacc[2 * ks][0],     sacc[2 * ks][1]);
                aP[ks][1] = packh2(sacc[2 * ks][2],     sacc[2 * ks][3]);
                aP[ks][2] = packh2(sacc[2 * ks + 1][0], sacc[2 * ks + 1][1]);
                aP[ks][3] = packh2(sacc[2 * ks + 1][2], sacc[2 * ks + 1][3]);
            }
#pragma unroll
            for (int ni = 0; ni < 8; ni++) {
                oacc[ni][0] *= al0; oacc[ni][1] *= al0;
                oacc[ni][2] *= al1; oacc[ni][3] *= al1;
            }
#pragma unroll
            for (int ks = 0; ks < 4; ks++)
#pragma unroll
                for (int ni2 = 0; ni2 < 4; ni2++) {
                    uint32_t vr[4];
                    ldsm_x4t(vr, vsb + (((ks * 16 + ((lane >> 3) & 1) * 8 + (lane & 7)) * FST
                                         + ni2 * 16 + (lane >> 4) * 8) << 1));
                    mma16816(oacc[ni2 * 2],     aP[ks], vr[0], vr[1]);
                    mma16816(oacc[ni2 * 2 + 1], aP[ks], vr[2], vr[3]);
                }
        }
        asm volatile("cp.async.wait_group 0;" ::: "memory");
        __syncthreads();
    }

    // epilogue: reduce per-lane l partials across the quad, normalize, store
    l0_ += __shfl_xor_sync(0xffffffffu, l0_, 1);
    l0_ += __shfl_xor_sync(0xffffffffu, l0_, 2);
    l1_ += __shfl_xor_sync(0xffffffffu, l1_, 1);
    l1_ += __shfl_xor_sync(0xffffffffu, l1_, 2);
    const float inv0 = 1.f / l0_, inv1 = 1.f / l1_;
    __half* ob = g_oh + (size_t)(b * Ss + qm0 + qw0) * (NH * HD) + h * HD;
#pragma unroll
    for (int ni = 0; ni < 8; ni++) {
        const int col = ni * 8 + tig * 2;
        __half2 o0 = __floats2half2_rn(oacc[ni][0] * inv0, oacc[ni][1] * inv0);
        __half2 o1 = __floats2half2_rn(oacc[ni][2] * inv1, oacc[ni][3] * inv1);
        *(__half2*)&ob[(size_t)gid * (NH * HD) + col]       = o0;
        *(__half2*)&ob[(size_t)(gid + 8) * (NH * HD) + col] = o1;
    }
}

// ---------------------------------------------------------------------------
extern "C" void kernel_launch(void* const* d_in, const int* in_sizes, int n_in,
                              void* d_out, int out_size) {
    const float* x  = (const float*)d_in[0];
    const float* Wq = (const float*)d_in[1];
    const float* Wk = (const float*)d_in[2];
    const float* Wv = (const float*)d_in[3];
    const float* Wo = (const float*)d_in[4];
    float* out = (float*)d_out;

    __half *xh, *wh, *woh, *oh;
    float* qkv;
    cudaGetSymbolAddress((void**)&xh,  g_xh);
    cudaGetSymbolAddress((void**)&wh,  g_wh);
    cudaGetSymbolAddress((void**)&woh, g_woh);
    cudaGetSymbolAddress((void**)&qkv, g_qkv);
    cudaGetSymbolAddress((void**)&oh,  g_oh);

    cudaFuncSetAttribute(flash_f16, cudaFuncAttributeMaxDynamicSharedMemorySize, FLASH_SMEM);

    convall<<<(1703936 + 255) / 256, 256>>>(x, Wq, Wk, Wv, Wo);
    gemm_f16<<<dim3(12, 32), 256>>>(xh, wh, qkv, 1536, 1024);
    prep<<<(MM * NH * 32 + MM * NKV * 32 + MM * NKV * 16 + 255) / 256, 256>>>(qkv);
    flash_f16<<<dim3(16, NH, Bb), 256, FLASH_SMEM>>>();
    gemm_f16<<<dim3(8, 32), 256>>>(oh, woh, out, 1024, 1024);
}